// round 5
// baseline (speedup 1.0000x reference)
#include <cuda_runtime.h>
#include <math.h>
#include <stdint.h>

// ---------------- problem constants ----------------
#define B_SZ   2
#define SEQL   2048
#define DM     2048
#define DI     4096
#define DS     128
#define HD     64
#define NH     64
#define CH     256
#define NC     8
#define CONV_DIM 4352           // DI + 2*DS
#define DPROJ    8512           // 2*DI + 2*DS + NH
#define EPSV   1e-5f
#define BL     (B_SZ * SEQL)    // 4096 rows

// ---------------- device scratch (static, no cudaMalloc) ----------------
__device__ float g_zxbcdt[(size_t)BL * DPROJ];     // in_proj output
__device__ float g_conv  [(size_t)BL * CONV_DIM];  // conv+silu output
__device__ float g_dt    [BL * NH];                // softplus(dt)
__device__ float g_acs   [B_SZ * NH * NC * CH];    // per-chunk cumsum(dA)
__device__ float g_states[B_SZ * NC * NH * HD * DS];
__device__ float g_prev  [B_SZ * NC * NH * HD * DS];
__device__ float g_y     [(size_t)BL * DI];        // Y then normalized y

// one dynamic-smem symbol shared by all kernels (aliased per launch)
extern __shared__ char dyn_smem[];

// ================= TF32 tensor-core GEMM (3xTF32 split) =================
// C[M,N] = A[M,K] * Bw[N,K]^T.  fp32 in/out, fp32-level accuracy.
// Block tile 128x128, K-step 32, 256 threads (8 warps, 2x4 -> 64x32 warp tile).
// hi/lo split done ONCE at STS time; smem holds interleaved float2 (hi, lo).

__device__ __forceinline__ void mma_tf32(float c[4], const uint32_t a[4],
                                         const uint32_t b[2])
{
    asm volatile(
        "mma.sync.aligned.m16n8k8.row.col.f32.tf32.tf32.f32 "
        "{%0,%1,%2,%3}, {%4,%5,%6,%7}, {%8,%9}, {%0,%1,%2,%3};\n"
        : "+f"(c[0]), "+f"(c[1]), "+f"(c[2]), "+f"(c[3])
        : "r"(a[0]), "r"(a[1]), "r"(a[2]), "r"(a[3]),
          "r"(b[0]), "r"(b[1]));
}

__device__ __forceinline__ float2 tf32_split2(float x)
{
    float hi = __uint_as_float(__float_as_uint(x) & 0xFFFFE000u);
    return make_float2(hi, x - hi);
}

#define GSTR2 36   // smem row stride in float2 units: (4g+tig) mod 16 conflict-free
#define GEMM_SMEM (2 * 128 * GSTR2 * (int)sizeof(float2))   // 73728 B

__global__ void __launch_bounds__(256) gemm_tf32_tn(const float* __restrict__ A,
                                                    const float* __restrict__ Bw,
                                                    float* __restrict__ C,
                                                    int M, int N, int K)
{
    float2* As = reinterpret_cast<float2*>(dyn_smem);                 // [128][GSTR2]
    float2* Bs = As + 128 * GSTR2;                                    // [128][GSTR2]

    const int tid  = threadIdx.x;
    const int warp = tid >> 5;
    const int lane = tid & 31;
    const int g    = lane >> 2;      // groupID 0..7
    const int tig  = lane & 3;       // thread-in-group 0..3
    const int wm   = warp >> 2;      // 0..1  -> 64-row slab
    const int wn   = warp & 3;       // 0..3  -> 32-col slab

    const int mBase = blockIdx.y * 128;
    const int nBase = blockIdx.x * 128;

    // GLD mapping: row r = tid>>1, k segment of 16
    const int r    = tid >> 1;
    const int kseg = (tid & 1) * 16;

    float acc[4][4][4];
#pragma unroll
    for (int mt = 0; mt < 4; mt++)
#pragma unroll
        for (int nt = 0; nt < 4; nt++)
#pragma unroll
            for (int e = 0; e < 4; e++) acc[mt][nt][e] = 0.f;

    const float* aRow = A  + (size_t)(mBase + r) * K + kseg;
    const int    gn   = nBase + r;
    const float* bRow = Bw + (size_t)gn * K + kseg;
    const bool   bOk  = (gn < N);

    float4 stgA[4], stgB[4];
#pragma unroll
    for (int j = 0; j < 4; j++) {
        stgA[j] = *reinterpret_cast<const float4*>(aRow + 4 * j);
        stgB[j] = bOk ? *reinterpret_cast<const float4*>(bRow + 4 * j)
                      : make_float4(0.f, 0.f, 0.f, 0.f);
    }

    for (int k0 = 0; k0 < K; k0 += 32) {
        __syncthreads();
        // split once, store interleaved (hi,lo)
#pragma unroll
        for (int j = 0; j < 4; j++) {
            int idx = r * GSTR2 + kseg + 4 * j;
            float2 a0 = tf32_split2(stgA[j].x), a1 = tf32_split2(stgA[j].y);
            float2 a2 = tf32_split2(stgA[j].z), a3 = tf32_split2(stgA[j].w);
            *reinterpret_cast<float4*>(&As[idx])     = make_float4(a0.x, a0.y, a1.x, a1.y);
            *reinterpret_cast<float4*>(&As[idx + 2]) = make_float4(a2.x, a2.y, a3.x, a3.y);
            float2 b0 = tf32_split2(stgB[j].x), b1 = tf32_split2(stgB[j].y);
            float2 b2 = tf32_split2(stgB[j].z), b3 = tf32_split2(stgB[j].w);
            *reinterpret_cast<float4*>(&Bs[idx])     = make_float4(b0.x, b0.y, b1.x, b1.y);
            *reinterpret_cast<float4*>(&Bs[idx + 2]) = make_float4(b2.x, b2.y, b3.x, b3.y);
        }
        __syncthreads();

        if (k0 + 32 < K) {
#pragma unroll
            for (int j = 0; j < 4; j++) {
                stgA[j] = *reinterpret_cast<const float4*>(aRow + k0 + 32 + 4 * j);
                stgB[j] = bOk ? *reinterpret_cast<const float4*>(bRow + k0 + 32 + 4 * j)
                              : make_float4(0.f, 0.f, 0.f, 0.f);
            }
        }

#pragma unroll
        for (int ks = 0; ks < 4; ks++) {
            const int kk = ks * 8;
            // B fragments: one LDS.64 fetches (hi, lo) together
            uint32_t bh[4][2], bl[4][2];
#pragma unroll
            for (int nt = 0; nt < 4; nt++) {
                int n = wn * 32 + nt * 8 + g;
                float2 b0 = Bs[n * GSTR2 + kk + tig];
                float2 b1 = Bs[n * GSTR2 + kk + tig + 4];
                bh[nt][0] = __float_as_uint(b0.x); bl[nt][0] = __float_as_uint(b0.y);
                bh[nt][1] = __float_as_uint(b1.x); bl[nt][1] = __float_as_uint(b1.y);
            }
#pragma unroll
            for (int mt = 0; mt < 4; mt++) {
                const int m0 = wm * 64 + mt * 16 + g;
                float2 A00 = As[m0 * GSTR2 + kk + tig];
                float2 A10 = As[(m0 + 8) * GSTR2 + kk + tig];
                float2 A01 = As[m0 * GSTR2 + kk + tig + 4];
                float2 A11 = As[(m0 + 8) * GSTR2 + kk + tig + 4];
                uint32_t ah[4] = { __float_as_uint(A00.x), __float_as_uint(A10.x),
                                   __float_as_uint(A01.x), __float_as_uint(A11.x) };
                uint32_t al[4] = { __float_as_uint(A00.y), __float_as_uint(A10.y),
                                   __float_as_uint(A01.y), __float_as_uint(A11.y) };
#pragma unroll
                for (int nt = 0; nt < 4; nt++) {
                    mma_tf32(acc[mt][nt], ah, bh[nt]);   // hi*hi
                    mma_tf32(acc[mt][nt], ah, bl[nt]);   // hi*lo
                    mma_tf32(acc[mt][nt], al, bh[nt]);   // lo*hi
                }
            }
        }
    }

    // epilogue
#pragma unroll
    for (int mt = 0; mt < 4; mt++) {
        const int row0 = mBase + wm * 64 + mt * 16 + g;
#pragma unroll
        for (int nt = 0; nt < 4; nt++) {
            const int col = nBase + wn * 32 + nt * 8 + 2 * tig;
            if (col < N) {
                float2 v01 = make_float2(acc[mt][nt][0], acc[mt][nt][1]);
                float2 v23 = make_float2(acc[mt][nt][2], acc[mt][nt][3]);
                *reinterpret_cast<float2*>(&C[(size_t)row0 * N + col])       = v01;
                *reinterpret_cast<float2*>(&C[(size_t)(row0 + 8) * N + col]) = v23;
            }
        }
    }
}

// ---------------- depthwise causal conv (width 4) + bias + silu ----------------
__global__ void conv_silu_kernel(const float* __restrict__ conv_w,
                                 const float* __restrict__ conv_b)
{
    int idx = blockIdx.x * blockDim.x + threadIdx.x;
    if (idx >= BL * CONV_DIM) return;
    int ch = idx % CONV_DIM;
    int l  = (idx / CONV_DIM) % SEQL;
    int b  = idx / (CONV_DIM * SEQL);
    float acc = conv_b[ch];
#pragma unroll
    for (int j = 0; j < 4; j++) {
        int t = l - 3 + j;
        if (t >= 0)
            acc = fmaf(conv_w[ch * 4 + j],
                       g_zxbcdt[(size_t)(b * SEQL + t) * DPROJ + DI + ch], acc);
    }
    g_conv[(size_t)(b * SEQL + l) * CONV_DIM + ch] = acc / (1.f + expf(-acc));
}

// ---------------- dt = softplus(raw + dt_bias) ----------------
__global__ void dt_kernel(const float* __restrict__ dt_bias)
{
    int idx = blockIdx.x * blockDim.x + threadIdx.x;
    if (idx >= BL * NH) return;
    int hh  = idx % NH;
    int row = idx / NH;
    float v = g_zxbcdt[(size_t)row * DPROJ + DI + CONV_DIM + hh] + dt_bias[hh];
    g_dt[idx] = (v > 20.f) ? v : log1pf(expf(v));
}

// ---------------- per-chunk inclusive cumsum of dA = dt * A ----------------
__global__ void scan_kernel(const float* __restrict__ A_log)
{
    const int bc = blockIdx.x;          // ((b*NH + h)*NC + c)
    const int c  = bc % NC;
    const int h  = (bc / NC) % NH;
    const int b  = bc / (NC * NH);
    const int l  = threadIdx.x;
    const float A = -expf(A_log[h]);
    float v = g_dt[(size_t)(b * SEQL + c * CH + l) * NH + h] * A;
    __shared__ float s[CH];
    s[l] = v;
    __syncthreads();
    for (int off = 1; off < CH; off <<= 1) {
        float t = (l >= off) ? s[l - off] : 0.f;
        __syncthreads();
        s[l] += t;
        __syncthreads();
    }
    g_acs[(size_t)bc * CH + l] = s[l];
}

// ---------------- per-chunk states ----------------
__global__ void __launch_bounds__(256) states_kernel()
{
    __shared__ float Bs[32][129];
    __shared__ float Xs[32][65];
    const int tid = threadIdx.x;
    const int tx  = tid & 15;
    const int ty  = tid >> 4;
    const int h = blockIdx.x % NH;
    const int c = (blockIdx.x / NH) % NC;
    const int b = blockIdx.x / (NH * NC);
    const size_t rowBase = (size_t)(b * SEQL + c * CH);
    const size_t acsBase = ((size_t)(b * NH + h) * NC + c) * CH;
    const float acsLast = g_acs[acsBase + CH - 1];

    float acc[4][8];
#pragma unroll
    for (int i = 0; i < 4; i++)
#pragma unroll
        for (int j = 0; j < 8; j++) acc[i][j] = 0.f;

    for (int s0 = 0; s0 < CH; s0 += 32) {
        __syncthreads();
#pragma unroll
        for (int it = 0; it < 4; it++) {
            int slot = tid + it * 256;
            int sr = slot >> 5;
            int n4 = (slot & 31) * 4;
            float4 v = *reinterpret_cast<const float4*>(
                &g_conv[(rowBase + s0 + sr) * CONV_DIM + DI + n4]);
            Bs[sr][n4 + 0] = v.x; Bs[sr][n4 + 1] = v.y;
            Bs[sr][n4 + 2] = v.z; Bs[sr][n4 + 3] = v.w;
        }
#pragma unroll
        for (int it = 0; it < 2; it++) {
            int slot = tid + it * 256;
            int sr = slot >> 4;
            int p4 = (slot & 15) * 4;
            size_t row = rowBase + s0 + sr;
            float sc = g_dt[row * NH + h] * expf(acsLast - g_acs[acsBase + s0 + sr]);
            float4 v = *reinterpret_cast<const float4*>(&g_conv[row * CONV_DIM + h * HD + p4]);
            Xs[sr][p4 + 0] = v.x * sc; Xs[sr][p4 + 1] = v.y * sc;
            Xs[sr][p4 + 2] = v.z * sc; Xs[sr][p4 + 3] = v.w * sc;
        }
        __syncthreads();
#pragma unroll 8
        for (int s = 0; s < 32; s++) {
            float a[4], bb[8];
#pragma unroll
            for (int i = 0; i < 4; i++) a[i] = Xs[s][ty * 4 + i];
#pragma unroll
            for (int j = 0; j < 4; j++) {
                bb[j]     = Bs[s][tx * 4 + j];
                bb[4 + j] = Bs[s][64 + tx * 4 + j];
            }
#pragma unroll
            for (int i = 0; i < 4; i++)
#pragma unroll
                for (int j = 0; j < 8; j++)
                    acc[i][j] = fmaf(a[i], bb[j], acc[i][j]);
        }
    }
    const size_t base = ((size_t)(b * NC + c) * NH + h) * (HD * DS);
#pragma unroll
    for (int i = 0; i < 4; i++) {
        int p = ty * 4 + i;
#pragma unroll
        for (int j = 0; j < 8; j++) {
            int n = (j < 4) ? (tx * 4 + j) : (64 + tx * 4 + j - 4);
            g_states[base + (size_t)p * DS + n] = acc[i][j];
        }
    }
}

// ---------------- inter-chunk recurrence ----------------
__global__ void chunk_rec_kernel()
{
    int idx = blockIdx.x * blockDim.x + threadIdx.x;
    if (idx >= B_SZ * NH * HD * DS) return;
    int n = idx % DS;
    int p = (idx / DS) % HD;
    int h = (idx / (DS * HD)) % NH;
    int b = idx / (DS * HD * NH);
    float prev = 0.f;
#pragma unroll
    for (int c = 0; c < NC; c++) {
        size_t off = (((size_t)(b * NC + c) * NH + h) * HD + p) * DS + n;
        g_prev[off] = prev;
        float cs = g_acs[((size_t)(b * NH + h) * NC + c) * CH + CH - 1];
        prev = expf(cs) * prev + g_states[off];
    }
}

// ---------------- SSD core ----------------
struct YS {
    float Cn [DS][129];
    float Bn [DS][33];
    float Pt [32][129];
    float Xd [32][65];
    float Pvn[DS][65];
    float acsl[128];
    float acss[32];
};

__global__ void __launch_bounds__(256) y_kernel(const float* __restrict__ Dvec)
{
    YS& S = *reinterpret_cast<YS*>(dyn_smem);
    const int tid = threadIdx.x;
    const int h  = blockIdx.x % NH;
    const int c  = (blockIdx.x / NH) % NC;
    const int b  = blockIdx.x / (NH * NC);
    const int lt = blockIdx.y;
    const size_t rowBase = (size_t)(b * SEQL + c * CH);
    const size_t acsBase = ((size_t)(b * NH + h) * NC + c) * CH;
    const int ly = tid >> 3;
    const int px = tid & 7;

#pragma unroll
    for (int it = 0; it < 16; it++) {
        int slot = tid + it * 256;
        int l  = slot >> 5;
        int n4 = (slot & 31) * 4;
        float4 v = *reinterpret_cast<const float4*>(
            &g_conv[(rowBase + lt * 128 + l) * CONV_DIM + DI + DS + n4]);
        S.Cn[n4 + 0][l] = v.x; S.Cn[n4 + 1][l] = v.y;
        S.Cn[n4 + 2][l] = v.z; S.Cn[n4 + 3][l] = v.w;
    }
    if (tid < 128) S.acsl[tid] = g_acs[acsBase + lt * 128 + tid];
    const size_t pvBase = ((size_t)(b * NC + c) * NH + h) * (HD * DS);
#pragma unroll
    for (int it = 0; it < 8; it++) {
        int slot = tid + it * 256;
        int p  = slot >> 5;
        int n4 = (slot & 31) * 4;
        float4 v = *reinterpret_cast<const float4*>(&g_prev[pvBase + (size_t)p * DS + n4]);
        S.Pvn[n4 + 0][p] = v.x; S.Pvn[n4 + 1][p] = v.y;
        S.Pvn[n4 + 2][p] = v.z; S.Pvn[n4 + 3][p] = v.w;
    }

    float yacc[4][8];
#pragma unroll
    for (int i = 0; i < 4; i++)
#pragma unroll
        for (int j = 0; j < 8; j++) yacc[i][j] = 0.f;

    const int nst = 4 * (lt + 1);
    for (int st = 0; st < nst; st++) {
        const int s0 = st * 32;
        __syncthreads();
#pragma unroll
        for (int it = 0; it < 4; it++) {
            int slot = tid + it * 256;
            int sr = slot >> 5;
            int n4 = (slot & 31) * 4;
            float4 v = *reinterpret_cast<const float4*>(
                &g_conv[(rowBase + s0 + sr) * CONV_DIM + DI + n4]);
            S.Bn[n4 + 0][sr] = v.x; S.Bn[n4 + 1][sr] = v.y;
            S.Bn[n4 + 2][sr] = v.z; S.Bn[n4 + 3][sr] = v.w;
        }
#pragma unroll
        for (int it = 0; it < 2; it++) {
            int slot = tid + it * 256;
            int sr = slot >> 4;
            int p4 = (slot & 15) * 4;
            size_t row = rowBase + s0 + sr;
            float dt = g_dt[row * NH + h];
            float4 v = *reinterpret_cast<const float4*>(&g_conv[row * CONV_DIM + h * HD + p4]);
            S.Xd[sr][p4 + 0] = v.x * dt; S.Xd[sr][p4 + 1] = v.y * dt;
            S.Xd[sr][p4 + 2] = v.z * dt; S.Xd[sr][p4 + 3] = v.w * dt;
        }
        if (tid < 32) S.acss[tid] = g_acs[acsBase + s0 + tid];
        __syncthreads();

        float sa[4][4];
#pragma unroll
        for (int i = 0; i < 4; i++)
#pragma unroll
            for (int j = 0; j < 4; j++) sa[i][j] = 0.f;
#pragma unroll 4
        for (int n = 0; n < DS; n++) {
            float a[4], bb[4];
#pragma unroll
            for (int i = 0; i < 4; i++) a[i]  = S.Cn[n][ly * 4 + i];
#pragma unroll
            for (int j = 0; j < 4; j++) bb[j] = S.Bn[n][px * 4 + j];
#pragma unroll
            for (int i = 0; i < 4; i++)
#pragma unroll
                for (int j = 0; j < 4; j++)
                    sa[i][j] = fmaf(a[i], bb[j], sa[i][j]);
        }
#pragma unroll
        for (int i = 0; i < 4; i++) {
            int l  = ly * 4 + i;
            int lg = lt * 128 + l;
            float al = S.acsl[l];
#pragma unroll
            for (int j = 0; j < 4; j++) {
                int sl = px * 4 + j;
                int sg = s0 + sl;
                float w = (sg <= lg) ? expf(al - S.acss[sl]) * sa[i][j] : 0.f;
                S.Pt[sl][l] = w;
            }
        }
        __syncthreads();
#pragma unroll 8
        for (int s = 0; s < 32; s++) {
            float a[4], bb[8];
#pragma unroll
            for (int i = 0; i < 4; i++) a[i] = S.Pt[s][ly * 4 + i];
#pragma unroll
            for (int j = 0; j < 4; j++) {
                bb[j]     = S.Xd[s][px * 4 + j];
                bb[4 + j] = S.Xd[s][32 + px * 4 + j];
            }
#pragma unroll
            for (int i = 0; i < 4; i++)
#pragma unroll
                for (int j = 0; j < 8; j++)
                    yacc[i][j] = fmaf(a[i], bb[j], yacc[i][j]);
        }
    }

    float oacc[4][8];
#pragma unroll
    for (int i = 0; i < 4; i++)
#pragma unroll
        for (int j = 0; j < 8; j++) oacc[i][j] = 0.f;
#pragma unroll 4
    for (int n = 0; n < DS; n++) {
        float a[4], bb[8];
#pragma unroll
        for (int i = 0; i < 4; i++) a[i] = S.Cn[n][ly * 4 + i];
#pragma unroll
        for (int j = 0; j < 4; j++) {
            bb[j]     = S.Pvn[n][px * 4 + j];
            bb[4 + j] = S.Pvn[n][32 + px * 4 + j];
        }
#pragma unroll
        for (int i = 0; i < 4; i++)
#pragma unroll
            for (int j = 0; j < 8; j++)
                oacc[i][j] = fmaf(a[i], bb[j], oacc[i][j]);
    }

    const float Dh = Dvec[h];
#pragma unroll
    for (int i = 0; i < 4; i++) {
        int l = ly * 4 + i;
        size_t row = rowBase + lt * 128 + l;
        float el = expf(S.acsl[l]);
#pragma unroll
        for (int j = 0; j < 8; j++) {
            int p = (j < 4) ? (px * 4 + j) : (32 + px * 4 + j - 4);
            float xs = g_conv[row * CONV_DIM + h * HD + p];
            g_y[row * DI + h * HD + p] = yacc[i][j] + el * oacc[i][j] + Dh * xs;
        }
    }
}

// ---------------- gate with silu(z) + RMSNorm ----------------
__global__ void __launch_bounds__(256) gate_norm_kernel(const float* __restrict__ norm_w)
{
    const int row = blockIdx.x;
    const float* yrow = &g_y[(size_t)row * DI];
    const float* zrow = &g_zxbcdt[(size_t)row * DPROJ];
    float vals[16];
    float ss = 0.f;
#pragma unroll
    for (int it = 0; it < 16; it++) {
        int i = threadIdx.x + it * 256;
        float z  = zrow[i];
        float yg = yrow[i] * (z / (1.f + expf(-z)));
        vals[it] = yg;
        ss = fmaf(yg, yg, ss);
    }
    __shared__ float red[8];
#pragma unroll
    for (int o = 16; o > 0; o >>= 1) ss += __shfl_xor_sync(0xffffffffu, ss, o);
    if ((threadIdx.x & 31) == 0) red[threadIdx.x >> 5] = ss;
    __syncthreads();
    float tot = 0.f;
#pragma unroll
    for (int w = 0; w < 8; w++) tot += red[w];
    float scale = rsqrtf(tot / (float)DI + EPSV);
    float* yw = &g_y[(size_t)row * DI];
#pragma unroll
    for (int it = 0; it < 16; it++) {
        int i = threadIdx.x + it * 256;
        yw[i] = vals[it] * scale * norm_w[i];
    }
}

// ---------------- launch ----------------
extern "C" void kernel_launch(void* const* d_in, const int* in_sizes, int n_in,
                              void* d_out, int out_size)
{
    (void)in_sizes; (void)n_in; (void)out_size;
    const float* x        = (const float*)d_in[0];
    const float* in_proj  = (const float*)d_in[1];
    const float* conv_w   = (const float*)d_in[2];
    const float* conv_b   = (const float*)d_in[3];
    const float* dt_bias  = (const float*)d_in[4];
    const float* A_log    = (const float*)d_in[5];
    const float* Dv       = (const float*)d_in[6];
    const float* norm_w   = (const float*)d_in[7];
    const float* out_proj = (const float*)d_in[8];
    float* out = (float*)d_out;

    float* zx = nullptr;
    float* yb = nullptr;
    cudaGetSymbolAddress((void**)&zx, g_zxbcdt);
    cudaGetSymbolAddress((void**)&yb, g_y);

    cudaFuncSetAttribute(y_kernel, cudaFuncAttributeMaxDynamicSharedMemorySize,
                         (int)sizeof(YS));
    cudaFuncSetAttribute(gemm_tf32_tn, cudaFuncAttributeMaxDynamicSharedMemorySize,
                         GEMM_SMEM);

    // 1. in_proj GEMM (tf32 tensor cores, 3xTF32): [BL, DPROJ] = x * W^T
    gemm_tf32_tn<<<dim3((DPROJ + 127) / 128, BL / 128), 256, GEMM_SMEM>>>(
        x, in_proj, zx, BL, DPROJ, DM);
    // 2. depthwise conv + silu
    conv_silu_kernel<<<(BL * CONV_DIM + 255) / 256, 256>>>(conv_w, conv_b);
    // 3. dt = softplus
    dt_kernel<<<(BL * NH + 255) / 256, 256>>>(dt_bias);
    // 4. per-chunk cumsum of dA
    scan_kernel<<<B_SZ * NH * NC, CH>>>(A_log);
    // 5. per-chunk states
    states_kernel<<<B_SZ * NC * NH, 256>>>();
    // 6. inter-chunk recurrence
    chunk_rec_kernel<<<(B_SZ * NH * HD * DS + 255) / 256, 256>>>();
    // 7. SSD core -> Y
    y_kernel<<<dim3(B_SZ * NC * NH, 2), 256, sizeof(YS)>>>(Dv);
    // 8. gate + RMSNorm
    gate_norm_kernel<<<BL, 256>>>(norm_w);
    // 9. out_proj GEMM (tf32 tensor cores, 3xTF32): out = y * W^T
    gemm_tf32_tn<<<dim3(DM / 128, BL / 128), 256, GEMM_SMEM>>>(
        yb, out_proj, out, BL, DM, DI);
}

// round 6
// speedup vs baseline: 2.2437x; 2.2437x over previous
#include <cuda_runtime.h>
#include <math.h>
#include <stdint.h>

// ---------------- problem constants ----------------
#define B_SZ   2
#define SEQL   2048
#define DM     2048
#define DI     4096
#define DS     128
#define HD     64
#define NH     64
#define CH     256
#define NC     8
#define CONV_DIM 4352           // DI + 2*DS
#define DPROJ    8512           // 2*DI + 2*DS + NH
#define EPSV   1e-5f
#define BL     (B_SZ * SEQL)    // 4096 rows

// ---------------- device scratch (static, no cudaMalloc) ----------------
__device__ float g_zxbcdt[(size_t)BL * DPROJ];     // in_proj output
__device__ float g_conv  [(size_t)BL * CONV_DIM];  // conv+silu output
__device__ float g_dt    [BL * NH];                // softplus(dt)
__device__ float g_acs   [B_SZ * NH * NC * CH];    // per-chunk cumsum(dA)
__device__ float g_states[B_SZ * NC * NH * HD * DS];
__device__ float g_prev  [B_SZ * NC * NH * HD * DS];
__device__ float g_y     [(size_t)BL * DI];        // Y then normalized y

extern __shared__ char dyn_smem[];   // used by y_kernel only

// ================= TF32 tensor-core GEMM (3xTF32, double-buffered) =======
// C[M,N] = A[M,K] * Bw[N,K]^T.  fp32 in/out, fp32-level accuracy.
// Block tile 128x128, K-step 16, 2 smem stages, 1 __syncthreads per step.
// 256 threads (8 warps, 2x4 -> 64x32 warp tile). 2 CTAs/SM.

__device__ __forceinline__ void mma_tf32(float c[4], const uint32_t a[4],
                                         const uint32_t b[2])
{
    asm volatile(
        "mma.sync.aligned.m16n8k8.row.col.f32.tf32.tf32.f32 "
        "{%0,%1,%2,%3}, {%4,%5,%6,%7}, {%8,%9}, {%0,%1,%2,%3};\n"
        : "+f"(c[0]), "+f"(c[1]), "+f"(c[2]), "+f"(c[3])
        : "r"(a[0]), "r"(a[1]), "r"(a[2]), "r"(a[3]),
          "r"(b[0]), "r"(b[1]));
}

// split x into tf32-representable hi (mantissa truncation) + exact residual lo
__device__ __forceinline__ void tf32_split(float x, uint32_t& hi, uint32_t& lo)
{
    uint32_t u = __float_as_uint(x) & 0xFFFFE000u;
    hi = u;
    lo = __float_as_uint(x - __uint_as_float(u));
}

#define KS   16   // K-step
#define LSTR 20   // smem row stride (floats): (20g + tig) mod 32 -> all 32 banks

__global__ void __launch_bounds__(256, 2) gemm_tf32_tn(const float* __restrict__ A,
                                                       const float* __restrict__ Bw,
                                                       float* __restrict__ C,
                                                       int M, int N, int K)
{
    __shared__ float As[2][128][LSTR];
    __shared__ float Bs[2][128][LSTR];

    const int tid  = threadIdx.x;
    const int warp = tid >> 5;
    const int lane = tid & 31;
    const int g    = lane >> 2;      // 0..7
    const int tig  = lane & 3;       // 0..3
    const int wm   = warp >> 2;      // 0..1  -> 64-row slab
    const int wn   = warp & 3;       // 0..3  -> 32-col slab

    const int mBase = blockIdx.y * 128;
    const int nBase = blockIdx.x * 128;

    // GLD mapping: 128 rows x 16 cols per matrix, 2 float4 per thread
    const int rL = tid >> 2;         // 0..63 ; second slot at +64
    const int c4 = (tid & 3) * 4;

    float acc[4][4][4];
#pragma unroll
    for (int mt = 0; mt < 4; mt++)
#pragma unroll
        for (int nt = 0; nt < 4; nt++)
#pragma unroll
            for (int e = 0; e < 4; e++) acc[mt][nt][e] = 0.f;

    const float* aP0 = A  + (size_t)(mBase + rL)      * K + c4;
    const float* aP1 = A  + (size_t)(mBase + rL + 64) * K + c4;
    const int    gn0 = nBase + rL;
    const int    gn1 = nBase + rL + 64;
    const float* bP0 = Bw + (size_t)gn0 * K + c4;
    const float* bP1 = Bw + (size_t)gn1 * K + c4;
    const bool   ok0 = (gn0 < N);
    const bool   ok1 = (gn1 < N);
    const float4 z4  = make_float4(0.f, 0.f, 0.f, 0.f);

    // prologue: stage 0
    {
        float4 a0 = *reinterpret_cast<const float4*>(aP0);
        float4 a1 = *reinterpret_cast<const float4*>(aP1);
        float4 b0 = ok0 ? *reinterpret_cast<const float4*>(bP0) : z4;
        float4 b1 = ok1 ? *reinterpret_cast<const float4*>(bP1) : z4;
        *reinterpret_cast<float4*>(&As[0][rL][c4])      = a0;
        *reinterpret_cast<float4*>(&As[0][rL + 64][c4]) = a1;
        *reinterpret_cast<float4*>(&Bs[0][rL][c4])      = b0;
        *reinterpret_cast<float4*>(&Bs[0][rL + 64][c4]) = b1;
    }
    __syncthreads();

    const int nk = K / KS;
    for (int kt = 0; kt < nk; kt++) {
        const int cur = kt & 1;
        float4 na0, na1, nb0, nb1;
        const bool more = (kt + 1 < nk);
        if (more) {
            const int kc = (kt + 1) * KS;
            na0 = *reinterpret_cast<const float4*>(aP0 + kc);
            na1 = *reinterpret_cast<const float4*>(aP1 + kc);
            nb0 = ok0 ? *reinterpret_cast<const float4*>(bP0 + kc) : z4;
            nb1 = ok1 ? *reinterpret_cast<const float4*>(bP1 + kc) : z4;
        }

        // compute on stage `cur` : 2 k-subtiles of 8
#pragma unroll
        for (int ks = 0; ks < 2; ks++) {
            const int kk = ks * 8;
            uint32_t bh[4][2], bl[4][2];
#pragma unroll
            for (int nt = 0; nt < 4; nt++) {
                const int n = wn * 32 + nt * 8 + g;
                float b0 = Bs[cur][n][kk + tig];
                float b1 = Bs[cur][n][kk + tig + 4];
                tf32_split(b0, bh[nt][0], bl[nt][0]);
                tf32_split(b1, bh[nt][1], bl[nt][1]);
            }
#pragma unroll
            for (int mt = 0; mt < 4; mt++) {
                const int m0 = wm * 64 + mt * 16 + g;
                uint32_t ah[4], al[4];
                float a0 = As[cur][m0][kk + tig];
                float a1 = As[cur][m0 + 8][kk + tig];
                float a2 = As[cur][m0][kk + tig + 4];
                float a3 = As[cur][m0 + 8][kk + tig + 4];
                tf32_split(a0, ah[0], al[0]);
                tf32_split(a1, ah[1], al[1]);
                tf32_split(a2, ah[2], al[2]);
                tf32_split(a3, ah[3], al[3]);
#pragma unroll
                for (int nt = 0; nt < 4; nt++) {
                    mma_tf32(acc[mt][nt], ah, bh[nt]);   // hi*hi
                    mma_tf32(acc[mt][nt], ah, bl[nt]);   // hi*lo
                    mma_tf32(acc[mt][nt], al, bh[nt]);   // lo*hi
                }
            }
        }

        if (more) {
            const int nxt = cur ^ 1;
            *reinterpret_cast<float4*>(&As[nxt][rL][c4])      = na0;
            *reinterpret_cast<float4*>(&As[nxt][rL + 64][c4]) = na1;
            *reinterpret_cast<float4*>(&Bs[nxt][rL][c4])      = nb0;
            *reinterpret_cast<float4*>(&Bs[nxt][rL + 64][c4]) = nb1;
        }
        __syncthreads();
    }

    // epilogue
#pragma unroll
    for (int mt = 0; mt < 4; mt++) {
        const int row0 = mBase + wm * 64 + mt * 16 + g;
#pragma unroll
        for (int nt = 0; nt < 4; nt++) {
            const int col = nBase + wn * 32 + nt * 8 + 2 * tig;
            if (col < N) {
                float2 v01 = make_float2(acc[mt][nt][0], acc[mt][nt][1]);
                float2 v23 = make_float2(acc[mt][nt][2], acc[mt][nt][3]);
                *reinterpret_cast<float2*>(&C[(size_t)row0 * N + col])       = v01;
                *reinterpret_cast<float2*>(&C[(size_t)(row0 + 8) * N + col]) = v23;
            }
        }
    }
}

// ---------------- depthwise causal conv (width 4) + bias + silu ----------------
__global__ void conv_silu_kernel(const float* __restrict__ conv_w,
                                 const float* __restrict__ conv_b)
{
    int idx = blockIdx.x * blockDim.x + threadIdx.x;
    if (idx >= BL * CONV_DIM) return;
    int ch = idx % CONV_DIM;
    int l  = (idx / CONV_DIM) % SEQL;
    int b  = idx / (CONV_DIM * SEQL);
    float acc = conv_b[ch];
#pragma unroll
    for (int j = 0; j < 4; j++) {
        int t = l - 3 + j;
        if (t >= 0)
            acc = fmaf(conv_w[ch * 4 + j],
                       g_zxbcdt[(size_t)(b * SEQL + t) * DPROJ + DI + ch], acc);
    }
    g_conv[(size_t)(b * SEQL + l) * CONV_DIM + ch] = acc / (1.f + expf(-acc));
}

// ---------------- dt = softplus(raw + dt_bias) ----------------
__global__ void dt_kernel(const float* __restrict__ dt_bias)
{
    int idx = blockIdx.x * blockDim.x + threadIdx.x;
    if (idx >= BL * NH) return;
    int hh  = idx % NH;
    int row = idx / NH;
    float v = g_zxbcdt[(size_t)row * DPROJ + DI + CONV_DIM + hh] + dt_bias[hh];
    g_dt[idx] = (v > 20.f) ? v : log1pf(expf(v));
}

// ---------------- per-chunk inclusive cumsum of dA = dt * A ----------------
__global__ void scan_kernel(const float* __restrict__ A_log)
{
    const int bc = blockIdx.x;          // ((b*NH + h)*NC + c)
    const int c  = bc % NC;
    const int h  = (bc / NC) % NH;
    const int b  = bc / (NC * NH);
    const int l  = threadIdx.x;
    const float A = -expf(A_log[h]);
    float v = g_dt[(size_t)(b * SEQL + c * CH + l) * NH + h] * A;
    __shared__ float s[CH];
    s[l] = v;
    __syncthreads();
    for (int off = 1; off < CH; off <<= 1) {
        float t = (l >= off) ? s[l - off] : 0.f;
        __syncthreads();
        s[l] += t;
        __syncthreads();
    }
    g_acs[(size_t)bc * CH + l] = s[l];
}

// ---------------- per-chunk states ----------------
__global__ void __launch_bounds__(256) states_kernel()
{
    __shared__ float Bs[32][129];
    __shared__ float Xs[32][65];
    const int tid = threadIdx.x;
    const int tx  = tid & 15;
    const int ty  = tid >> 4;
    const int h = blockIdx.x % NH;
    const int c = (blockIdx.x / NH) % NC;
    const int b = blockIdx.x / (NH * NC);
    const size_t rowBase = (size_t)(b * SEQL + c * CH);
    const size_t acsBase = ((size_t)(b * NH + h) * NC + c) * CH;
    const float acsLast = g_acs[acsBase + CH - 1];

    float acc[4][8];
#pragma unroll
    for (int i = 0; i < 4; i++)
#pragma unroll
        for (int j = 0; j < 8; j++) acc[i][j] = 0.f;

    for (int s0 = 0; s0 < CH; s0 += 32) {
        __syncthreads();
#pragma unroll
        for (int it = 0; it < 4; it++) {
            int slot = tid + it * 256;
            int sr = slot >> 5;
            int n4 = (slot & 31) * 4;
            float4 v = *reinterpret_cast<const float4*>(
                &g_conv[(rowBase + s0 + sr) * CONV_DIM + DI + n4]);
            Bs[sr][n4 + 0] = v.x; Bs[sr][n4 + 1] = v.y;
            Bs[sr][n4 + 2] = v.z; Bs[sr][n4 + 3] = v.w;
        }
#pragma unroll
        for (int it = 0; it < 2; it++) {
            int slot = tid + it * 256;
            int sr = slot >> 4;
            int p4 = (slot & 15) * 4;
            size_t row = rowBase + s0 + sr;
            float sc = g_dt[row * NH + h] * expf(acsLast - g_acs[acsBase + s0 + sr]);
            float4 v = *reinterpret_cast<const float4*>(&g_conv[row * CONV_DIM + h * HD + p4]);
            Xs[sr][p4 + 0] = v.x * sc; Xs[sr][p4 + 1] = v.y * sc;
            Xs[sr][p4 + 2] = v.z * sc; Xs[sr][p4 + 3] = v.w * sc;
        }
        __syncthreads();
#pragma unroll 8
        for (int s = 0; s < 32; s++) {
            float a[4], bb[8];
#pragma unroll
            for (int i = 0; i < 4; i++) a[i] = Xs[s][ty * 4 + i];
#pragma unroll
            for (int j = 0; j < 4; j++) {
                bb[j]     = Bs[s][tx * 4 + j];
                bb[4 + j] = Bs[s][64 + tx * 4 + j];
            }
#pragma unroll
            for (int i = 0; i < 4; i++)
#pragma unroll
                for (int j = 0; j < 8; j++)
                    acc[i][j] = fmaf(a[i], bb[j], acc[i][j]);
        }
    }
    const size_t base = ((size_t)(b * NC + c) * NH + h) * (HD * DS);
#pragma unroll
    for (int i = 0; i < 4; i++) {
        int p = ty * 4 + i;
#pragma unroll
        for (int j = 0; j < 8; j++) {
            int n = (j < 4) ? (tx * 4 + j) : (64 + tx * 4 + j - 4);
            g_states[base + (size_t)p * DS + n] = acc[i][j];
        }
    }
}

// ---------------- inter-chunk recurrence ----------------
__global__ void chunk_rec_kernel()
{
    int idx = blockIdx.x * blockDim.x + threadIdx.x;
    if (idx >= B_SZ * NH * HD * DS) return;
    int n = idx % DS;
    int p = (idx / DS) % HD;
    int h = (idx / (DS * HD)) % NH;
    int b = idx / (DS * HD * NH);
    float prev = 0.f;
#pragma unroll
    for (int c = 0; c < NC; c++) {
        size_t off = (((size_t)(b * NC + c) * NH + h) * HD + p) * DS + n;
        g_prev[off] = prev;
        float cs = g_acs[((size_t)(b * NH + h) * NC + c) * CH + CH - 1];
        prev = expf(cs) * prev + g_states[off];
    }
}

// ---------------- SSD core ----------------
struct YS {
    float Cn [DS][129];
    float Bn [DS][33];
    float Pt [32][129];
    float Xd [32][65];
    float Pvn[DS][65];
    float acsl[128];
    float acss[32];
};

__global__ void __launch_bounds__(256) y_kernel(const float* __restrict__ Dvec)
{
    YS& S = *reinterpret_cast<YS*>(dyn_smem);
    const int tid = threadIdx.x;
    const int h  = blockIdx.x % NH;
    const int c  = (blockIdx.x / NH) % NC;
    const int b  = blockIdx.x / (NH * NC);
    const int lt = blockIdx.y;
    const size_t rowBase = (size_t)(b * SEQL + c * CH);
    const size_t acsBase = ((size_t)(b * NH + h) * NC + c) * CH;
    const int ly = tid >> 3;
    const int px = tid & 7;

#pragma unroll
    for (int it = 0; it < 16; it++) {
        int slot = tid + it * 256;
        int l  = slot >> 5;
        int n4 = (slot & 31) * 4;
        float4 v = *reinterpret_cast<const float4*>(
            &g_conv[(rowBase + lt * 128 + l) * CONV_DIM + DI + DS + n4]);
        S.Cn[n4 + 0][l] = v.x; S.Cn[n4 + 1][l] = v.y;
        S.Cn[n4 + 2][l] = v.z; S.Cn[n4 + 3][l] = v.w;
    }
    if (tid < 128) S.acsl[tid] = g_acs[acsBase + lt * 128 + tid];
    const size_t pvBase = ((size_t)(b * NC + c) * NH + h) * (HD * DS);
#pragma unroll
    for (int it = 0; it < 8; it++) {
        int slot = tid + it * 256;
        int p  = slot >> 5;
        int n4 = (slot & 31) * 4;
        float4 v = *reinterpret_cast<const float4*>(&g_prev[pvBase + (size_t)p * DS + n4]);
        S.Pvn[n4 + 0][p] = v.x; S.Pvn[n4 + 1][p] = v.y;
        S.Pvn[n4 + 2][p] = v.z; S.Pvn[n4 + 3][p] = v.w;
    }

    float yacc[4][8];
#pragma unroll
    for (int i = 0; i < 4; i++)
#pragma unroll
        for (int j = 0; j < 8; j++) yacc[i][j] = 0.f;

    const int nst = 4 * (lt + 1);
    for (int st = 0; st < nst; st++) {
        const int s0 = st * 32;
        __syncthreads();
#pragma unroll
        for (int it = 0; it < 4; it++) {
            int slot = tid + it * 256;
            int sr = slot >> 5;
            int n4 = (slot & 31) * 4;
            float4 v = *reinterpret_cast<const float4*>(
                &g_conv[(rowBase + s0 + sr) * CONV_DIM + DI + n4]);
            S.Bn[n4 + 0][sr] = v.x; S.Bn[n4 + 1][sr] = v.y;
            S.Bn[n4 + 2][sr] = v.z; S.Bn[n4 + 3][sr] = v.w;
        }
#pragma unroll
        for (int it = 0; it < 2; it++) {
            int slot = tid + it * 256;
            int sr = slot >> 4;
            int p4 = (slot & 15) * 4;
            size_t row = rowBase + s0 + sr;
            float dt = g_dt[row * NH + h];
            float4 v = *reinterpret_cast<const float4*>(&g_conv[row * CONV_DIM + h * HD + p4]);
            S.Xd[sr][p4 + 0] = v.x * dt; S.Xd[sr][p4 + 1] = v.y * dt;
            S.Xd[sr][p4 + 2] = v.z * dt; S.Xd[sr][p4 + 3] = v.w * dt;
        }
        if (tid < 32) S.acss[tid] = g_acs[acsBase + s0 + tid];
        __syncthreads();

        float sa[4][4];
#pragma unroll
        for (int i = 0; i < 4; i++)
#pragma unroll
            for (int j = 0; j < 4; j++) sa[i][j] = 0.f;
#pragma unroll 4
        for (int n = 0; n < DS; n++) {
            float a[4], bb[4];
#pragma unroll
            for (int i = 0; i < 4; i++) a[i]  = S.Cn[n][ly * 4 + i];
#pragma unroll
            for (int j = 0; j < 4; j++) bb[j] = S.Bn[n][px * 4 + j];
#pragma unroll
            for (int i = 0; i < 4; i++)
#pragma unroll
                for (int j = 0; j < 4; j++)
                    sa[i][j] = fmaf(a[i], bb[j], sa[i][j]);
        }
#pragma unroll
        for (int i = 0; i < 4; i++) {
            int l  = ly * 4 + i;
            int lg = lt * 128 + l;
            float al = S.acsl[l];
#pragma unroll
            for (int j = 0; j < 4; j++) {
                int sl = px * 4 + j;
                int sg = s0 + sl;
                float w = (sg <= lg) ? expf(al - S.acss[sl]) * sa[i][j] : 0.f;
                S.Pt[sl][l] = w;
            }
        }
        __syncthreads();
#pragma unroll 8
        for (int s = 0; s < 32; s++) {
            float a[4], bb[8];
#pragma unroll
            for (int i = 0; i < 4; i++) a[i] = S.Pt[s][ly * 4 + i];
#pragma unroll
            for (int j = 0; j < 4; j++) {
                bb[j]     = S.Xd[s][px * 4 + j];
                bb[4 + j] = S.Xd[s][32 + px * 4 + j];
            }
#pragma unroll
            for (int i = 0; i < 4; i++)
#pragma unroll
                for (int j = 0; j < 8; j++)
                    yacc[i][j] = fmaf(a[i], bb[j], yacc[i][j]);
        }
    }

    float oacc[4][8];
#pragma unroll
    for (int i = 0; i < 4; i++)
#pragma unroll
        for (int j = 0; j < 8; j++) oacc[i][j] = 0.f;
#pragma unroll 4
    for (int n = 0; n < DS; n++) {
        float a[4], bb[8];
#pragma unroll
        for (int i = 0; i < 4; i++) a[i] = S.Cn[n][ly * 4 + i];
#pragma unroll
        for (int j = 0; j < 4; j++) {
            bb[j]     = S.Pvn[n][px * 4 + j];
            bb[4 + j] = S.Pvn[n][32 + px * 4 + j];
        }
#pragma unroll
        for (int i = 0; i < 4; i++)
#pragma unroll
            for (int j = 0; j < 8; j++)
                oacc[i][j] = fmaf(a[i], bb[j], oacc[i][j]);
    }

    const float Dh = Dvec[h];
#pragma unroll
    for (int i = 0; i < 4; i++) {
        int l = ly * 4 + i;
        size_t row = rowBase + lt * 128 + l;
        float el = expf(S.acsl[l]);
#pragma unroll
        for (int j = 0; j < 8; j++) {
            int p = (j < 4) ? (px * 4 + j) : (32 + px * 4 + j - 4);
            float xs = g_conv[row * CONV_DIM + h * HD + p];
            g_y[row * DI + h * HD + p] = yacc[i][j] + el * oacc[i][j] + Dh * xs;
        }
    }
}

// ---------------- gate with silu(z) + RMSNorm ----------------
__global__ void __launch_bounds__(256) gate_norm_kernel(const float* __restrict__ norm_w)
{
    const int row = blockIdx.x;
    const float* yrow = &g_y[(size_t)row * DI];
    const float* zrow = &g_zxbcdt[(size_t)row * DPROJ];
    float vals[16];
    float ss = 0.f;
#pragma unroll
    for (int it = 0; it < 16; it++) {
        int i = threadIdx.x + it * 256;
        float z  = zrow[i];
        float yg = yrow[i] * (z / (1.f + expf(-z)));
        vals[it] = yg;
        ss = fmaf(yg, yg, ss);
    }
    __shared__ float red[8];
#pragma unroll
    for (int o = 16; o > 0; o >>= 1) ss += __shfl_xor_sync(0xffffffffu, ss, o);
    if ((threadIdx.x & 31) == 0) red[threadIdx.x >> 5] = ss;
    __syncthreads();
    float tot = 0.f;
#pragma unroll
    for (int w = 0; w < 8; w++) tot += red[w];
    float scale = rsqrtf(tot / (float)DI + EPSV);
    float* yw = &g_y[(size_t)row * DI];
#pragma unroll
    for (int it = 0; it < 16; it++) {
        int i = threadIdx.x + it * 256;
        yw[i] = vals[it] * scale * norm_w[i];
    }
}

// ---------------- launch ----------------
extern "C" void kernel_launch(void* const* d_in, const int* in_sizes, int n_in,
                              void* d_out, int out_size)
{
    (void)in_sizes; (void)n_in; (void)out_size;
    const float* x        = (const float*)d_in[0];
    const float* in_proj  = (const float*)d_in[1];
    const float* conv_w   = (const float*)d_in[2];
    const float* conv_b   = (const float*)d_in[3];
    const float* dt_bias  = (const float*)d_in[4];
    const float* A_log    = (const float*)d_in[5];
    const float* Dv       = (const float*)d_in[6];
    const float* norm_w   = (const float*)d_in[7];
    const float* out_proj = (const float*)d_in[8];
    float* out = (float*)d_out;

    float* zx = nullptr;
    float* yb = nullptr;
    cudaGetSymbolAddress((void**)&zx, g_zxbcdt);
    cudaGetSymbolAddress((void**)&yb, g_y);

    cudaFuncSetAttribute(y_kernel, cudaFuncAttributeMaxDynamicSharedMemorySize,
                         (int)sizeof(YS));

    // 1. in_proj GEMM (3xTF32, double-buffered): [BL, DPROJ] = x * W^T
    gemm_tf32_tn<<<dim3((DPROJ + 127) / 128, BL / 128), 256>>>(x, in_proj, zx, BL, DPROJ, DM);
    // 2. depthwise conv + silu
    conv_silu_kernel<<<(BL * CONV_DIM + 255) / 256, 256>>>(conv_w, conv_b);
    // 3. dt = softplus
    dt_kernel<<<(BL * NH + 255) / 256, 256>>>(dt_bias);
    // 4. per-chunk cumsum of dA
    scan_kernel<<<B_SZ * NH * NC, CH>>>(A_log);
    // 5. per-chunk states
    states_kernel<<<B_SZ * NC * NH, 256>>>();
    // 6. inter-chunk recurrence
    chunk_rec_kernel<<<(B_SZ * NH * HD * DS + 255) / 256, 256>>>();
    // 7. SSD core -> Y
    y_kernel<<<dim3(B_SZ * NC * NH, 2), 256, sizeof(YS)>>>(Dv);
    // 8. gate + RMSNorm
    gate_norm_kernel<<<BL, 256>>>(norm_w);
    // 9. out_proj GEMM (3xTF32, double-buffered): out = y * W^T
    gemm_tf32_tn<<<dim3(DM / 128, BL / 128), 256>>>(yb, out_proj, out, BL, DM, DI);
}